// round 7
// baseline (speedup 1.0000x reference)
#include <cuda_runtime.h>
#include <cuda_bf16.h>

// Cosine similarity per row: out[i] = dot(q_i, d_i) / (||q_i|| * ||d_i||)
// N = 262144 rows, D = 256 fp32.
// Persistent kernel, one row per warp per iteration (4 front-batched LDG.128),
// grid-stride by total warp count so consecutive warps always cover adjacent
// rows (DRAM page locality), #pragma unroll 1 to keep each front batch local.

#define D_DIM 256
#define D4 (D_DIM / 4)
#define THREADS_PER_BLOCK 256
#define GRID_BLOCKS (148 * 8)

__global__ __launch_bounds__(THREADS_PER_BLOCK, 8)
void cosine_sim_kernel(const float4* __restrict__ q4,
                       const float4* __restrict__ d4,
                       float* __restrict__ out,
                       int n_rows) {
    const int lane = threadIdx.x & 31;
    const int gwarp = (blockIdx.x * THREADS_PER_BLOCK + threadIdx.x) >> 5;
    const int nwarps = (GRID_BLOCKS * THREADS_PER_BLOCK) >> 5;

    #pragma unroll 1
    for (int row = gwarp; row < n_rows; row += nwarps) {
        const float4* qr = q4 + (size_t)row * D4;
        const float4* dr = d4 + (size_t)row * D4;

        // Front-batch the 4 LDG.128 for this row, interleaving q/d streams.
        float4 qa = __ldcs(qr + lane);
        float4 da = __ldcs(dr + lane);
        float4 qb = __ldcs(qr + lane + 32);
        float4 db = __ldcs(dr + lane + 32);

        float dot = qa.x * da.x + qa.y * da.y + qa.z * da.z + qa.w * da.w
                  + qb.x * db.x + qb.y * db.y + qb.z * db.z + qb.w * db.w;
        float qq  = qa.x * qa.x + qa.y * qa.y + qa.z * qa.z + qa.w * qa.w
                  + qb.x * qb.x + qb.y * qb.y + qb.z * qb.z + qb.w * qb.w;
        float dd  = da.x * da.x + da.y * da.y + da.z * da.z + da.w * da.w
                  + db.x * db.x + db.y * db.y + db.z * db.z + db.w * db.w;

        // Warp butterfly reduction of the three partial sums.
        #pragma unroll
        for (int off = 16; off > 0; off >>= 1) {
            dot += __shfl_xor_sync(0xFFFFFFFFu, dot, off);
            qq  += __shfl_xor_sync(0xFFFFFFFFu, qq,  off);
            dd  += __shfl_xor_sync(0xFFFFFFFFu, dd,  off);
        }

        if (lane == 0) {
            __stcs(out + row, dot * rsqrtf(qq * dd));
        }
    }
}

extern "C" void kernel_launch(void* const* d_in, const int* in_sizes, int n_in,
                              void* d_out, int out_size) {
    const float4* q = (const float4*)d_in[0];
    const float4* d = (const float4*)d_in[1];
    float* out = (float*)d_out;

    const int n_rows = in_sizes[0] / D_DIM;

    cosine_sim_kernel<<<GRID_BLOCKS, THREADS_PER_BLOCK>>>(q, d, out, n_rows);
}

// round 8
// speedup vs baseline: 1.0446x; 1.0446x over previous
#include <cuda_runtime.h>
#include <cuda_bf16.h>

// Cosine similarity per row: out[i] = dot(q_i, d_i) / (||q_i|| * ||d_i||)
// N = 262144 rows, D = 256 fp32.
// Classic (non-persistent) launch, but each block owns a contiguous 32-row
// chunk: 8 warps x 4 iterations, one row per warp per iteration with 4
// front-batched LDG.128. CTA issue order keeps the global access front a
// tight sliding window (the property that round 6 showed is what matters);
// 4 iterations per block cuts block-churn 4x.

#define D_DIM 256
#define D4 (D_DIM / 4)
#define THREADS_PER_BLOCK 256
#define WARPS_PER_BLOCK (THREADS_PER_BLOCK / 32)
#define ITERS 4
#define ROWS_PER_BLOCK (WARPS_PER_BLOCK * ITERS)   // 32

__global__ __launch_bounds__(THREADS_PER_BLOCK, 8)
void cosine_sim_kernel(const float4* __restrict__ q4,
                       const float4* __restrict__ d4,
                       float* __restrict__ out,
                       int n_rows) {
    const int lane = threadIdx.x & 31;
    const int warp = threadIdx.x >> 5;
    const int base = blockIdx.x * ROWS_PER_BLOCK + warp;

    #pragma unroll 1
    for (int i = 0; i < ITERS; i++) {
        const int row = base + i * WARPS_PER_BLOCK;
        if (row >= n_rows) break;

        const float4* qr = q4 + (size_t)row * D4;
        const float4* dr = d4 + (size_t)row * D4;

        // Front-batch the 4 LDG.128 for this row, interleaving q/d streams.
        float4 qa = __ldcs(qr + lane);
        float4 da = __ldcs(dr + lane);
        float4 qb = __ldcs(qr + lane + 32);
        float4 db = __ldcs(dr + lane + 32);

        float dot = qa.x * da.x + qa.y * da.y + qa.z * da.z + qa.w * da.w
                  + qb.x * db.x + qb.y * db.y + qb.z * db.z + qb.w * db.w;
        float qq  = qa.x * qa.x + qa.y * qa.y + qa.z * qa.z + qa.w * qa.w
                  + qb.x * qb.x + qb.y * qb.y + qb.z * qb.z + qb.w * qb.w;
        float dd  = da.x * da.x + da.y * da.y + da.z * da.z + da.w * da.w
                  + db.x * db.x + db.y * db.y + db.z * db.z + db.w * db.w;

        // Warp butterfly reduction of the three partial sums.
        #pragma unroll
        for (int off = 16; off > 0; off >>= 1) {
            dot += __shfl_xor_sync(0xFFFFFFFFu, dot, off);
            qq  += __shfl_xor_sync(0xFFFFFFFFu, qq,  off);
            dd  += __shfl_xor_sync(0xFFFFFFFFu, dd,  off);
        }

        if (lane == 0) {
            __stcs(out + row, dot * rsqrtf(qq * dd));
        }
    }
}

extern "C" void kernel_launch(void* const* d_in, const int* in_sizes, int n_in,
                              void* d_out, int out_size) {
    const float4* q = (const float4*)d_in[0];
    const float4* d = (const float4*)d_in[1];
    float* out = (float*)d_out;

    const int n_rows = in_sizes[0] / D_DIM;
    const int blocks = (n_rows + ROWS_PER_BLOCK - 1) / ROWS_PER_BLOCK;

    cosine_sim_kernel<<<blocks, THREADS_PER_BLOCK>>>(q, d, out, n_rows);
}

// round 9
// speedup vs baseline: 1.0523x; 1.0074x over previous
#include <cuda_runtime.h>
#include <cuda_bf16.h>

// Cosine similarity per row: out[i] = dot(q_i, d_i) / (||q_i|| * ||d_i||)
// N = 262144 rows, D = 256 fp32.
// Classic launch; each block owns a contiguous 64-row chunk: 8 warps x 8
// iterations, one row per warp per iteration with 4 front-batched LDG.128.
// Contiguous chunks + in-order CTA issue keep the global access front a
// tight sliding window (the controlling variable per rounds 6-7); larger
// chunks cut block-churn further.

#define D_DIM 256
#define D4 (D_DIM / 4)
#define THREADS_PER_BLOCK 256
#define WARPS_PER_BLOCK (THREADS_PER_BLOCK / 32)
#define ITERS 8
#define ROWS_PER_BLOCK (WARPS_PER_BLOCK * ITERS)   // 64

__global__ __launch_bounds__(THREADS_PER_BLOCK, 8)
void cosine_sim_kernel(const float4* __restrict__ q4,
                       const float4* __restrict__ d4,
                       float* __restrict__ out,
                       int n_rows) {
    const int lane = threadIdx.x & 31;
    const int warp = threadIdx.x >> 5;
    const int base = blockIdx.x * ROWS_PER_BLOCK + warp;

    #pragma unroll 1
    for (int i = 0; i < ITERS; i++) {
        const int row = base + i * WARPS_PER_BLOCK;
        if (row >= n_rows) break;

        const float4* qr = q4 + (size_t)row * D4;
        const float4* dr = d4 + (size_t)row * D4;

        // Front-batch the 4 LDG.128 for this row, interleaving q/d streams.
        float4 qa = __ldcs(qr + lane);
        float4 da = __ldcs(dr + lane);
        float4 qb = __ldcs(qr + lane + 32);
        float4 db = __ldcs(dr + lane + 32);

        float dot = qa.x * da.x + qa.y * da.y + qa.z * da.z + qa.w * da.w
                  + qb.x * db.x + qb.y * db.y + qb.z * db.z + qb.w * db.w;
        float qq  = qa.x * qa.x + qa.y * qa.y + qa.z * qa.z + qa.w * qa.w
                  + qb.x * qb.x + qb.y * qb.y + qb.z * qb.z + qb.w * qb.w;
        float dd  = da.x * da.x + da.y * da.y + da.z * da.z + da.w * da.w
                  + db.x * db.x + db.y * db.y + db.z * db.z + db.w * db.w;

        // Warp butterfly reduction of the three partial sums.
        #pragma unroll
        for (int off = 16; off > 0; off >>= 1) {
            dot += __shfl_xor_sync(0xFFFFFFFFu, dot, off);
            qq  += __shfl_xor_sync(0xFFFFFFFFu, qq,  off);
            dd  += __shfl_xor_sync(0xFFFFFFFFu, dd,  off);
        }

        if (lane == 0) {
            __stcs(out + row, dot * rsqrtf(qq * dd));
        }
    }
}

extern "C" void kernel_launch(void* const* d_in, const int* in_sizes, int n_in,
                              void* d_out, int out_size) {
    const float4* q = (const float4*)d_in[0];
    const float4* d = (const float4*)d_in[1];
    float* out = (float*)d_out;

    const int n_rows = in_sizes[0] / D_DIM;
    const int blocks = (n_rows + ROWS_PER_BLOCK - 1) / ROWS_PER_BLOCK;

    cosine_sim_kernel<<<blocks, THREADS_PER_BLOCK>>>(q, d, out, n_rows);
}

// round 10
// speedup vs baseline: 1.0527x; 1.0004x over previous
#include <cuda_runtime.h>
#include <cuda_bf16.h>

// Cosine similarity per row: out[i] = dot(q_i, d_i) / (||q_i|| * ||d_i||)
// N = 262144 rows, D = 256 fp32.
// Classic launch; each block owns a contiguous 32-row chunk: 8 warps x 4
// iterations, one row per warp per iteration with 4 front-batched LDG.128
// (streaming hints). This shape measured best DRAM efficiency of the
// session (88.3%, 7.00 TB/s). Full blocks take a branch-free loop; only a
// possible ragged last block checks bounds.

#define D_DIM 256
#define D4 (D_DIM / 4)
#define THREADS_PER_BLOCK 256
#define WARPS_PER_BLOCK (THREADS_PER_BLOCK / 32)
#define ITERS 4
#define ROWS_PER_BLOCK (WARPS_PER_BLOCK * ITERS)   // 32

__device__ __forceinline__ void do_row(const float4* __restrict__ qr,
                                       const float4* __restrict__ dr,
                                       float* __restrict__ out, int row, int lane) {
    // Front-batch the 4 LDG.128 for this row, interleaving q/d streams.
    float4 qa = __ldcs(qr + lane);
    float4 da = __ldcs(dr + lane);
    float4 qb = __ldcs(qr + lane + 32);
    float4 db = __ldcs(dr + lane + 32);

    float dot = qa.x * da.x + qa.y * da.y + qa.z * da.z + qa.w * da.w
              + qb.x * db.x + qb.y * db.y + qb.z * db.z + qb.w * db.w;
    float qq  = qa.x * qa.x + qa.y * qa.y + qa.z * qa.z + qa.w * qa.w
              + qb.x * qb.x + qb.y * qb.y + qb.z * qb.z + qb.w * qb.w;
    float dd  = da.x * da.x + da.y * da.y + da.z * da.z + da.w * da.w
              + db.x * db.x + db.y * db.y + db.z * db.z + db.w * db.w;

    #pragma unroll
    for (int off = 16; off > 0; off >>= 1) {
        dot += __shfl_xor_sync(0xFFFFFFFFu, dot, off);
        qq  += __shfl_xor_sync(0xFFFFFFFFu, qq,  off);
        dd  += __shfl_xor_sync(0xFFFFFFFFu, dd,  off);
    }

    if (lane == 0) {
        __stcs(out + row, dot * rsqrtf(qq * dd));
    }
}

__global__ __launch_bounds__(THREADS_PER_BLOCK, 8)
void cosine_sim_kernel(const float4* __restrict__ q4,
                       const float4* __restrict__ d4,
                       float* __restrict__ out,
                       int n_rows) {
    const int lane = threadIdx.x & 31;
    const int warp = threadIdx.x >> 5;
    const int base = blockIdx.x * ROWS_PER_BLOCK + warp;

    if (base + (ITERS - 1) * WARPS_PER_BLOCK < n_rows) {
        // Full block: branch-free, pointers advance by increment.
        int row = base;
        const float4* qr = q4 + (size_t)row * D4;
        const float4* dr = d4 + (size_t)row * D4;
        #pragma unroll 1
        for (int i = 0; i < ITERS; i++) {
            do_row(qr, dr, out, row, lane);
            row += WARPS_PER_BLOCK;
            qr  += WARPS_PER_BLOCK * D4;
            dr  += WARPS_PER_BLOCK * D4;
        }
    } else {
        #pragma unroll 1
        for (int i = 0; i < ITERS; i++) {
            const int row = base + i * WARPS_PER_BLOCK;
            if (row >= n_rows) break;
            do_row(q4 + (size_t)row * D4, d4 + (size_t)row * D4, out, row, lane);
        }
    }
}

extern "C" void kernel_launch(void* const* d_in, const int* in_sizes, int n_in,
                              void* d_out, int out_size) {
    const float4* q = (const float4*)d_in[0];
    const float4* d = (const float4*)d_in[1];
    float* out = (float*)d_out;

    const int n_rows = in_sizes[0] / D_DIM;
    const int blocks = (n_rows + ROWS_PER_BLOCK - 1) / ROWS_PER_BLOCK;

    cosine_sim_kernel<<<blocks, THREADS_PER_BLOCK>>>(q, d, out, n_rows);
}